// round 1
// baseline (speedup 1.0000x reference)
#include <cuda_runtime.h>
#include <math.h>

#define NB 16
#define FDIM 256
#define KEEP 100
#define NCAND (KEEP * FDIM)   // 25600

// ---------------- scratch (static device globals; no allocations) ----------------
__device__ float gU[3][256][32];            // U_l[i][h] = sum_o s_w1[h,o] * W_l[o,i]
__device__ float gScore0[NB][256];
__device__ int   gSelIdx[3][NB][KEEP];      // selected candidate index per stage
__device__ float gSelVal[3][NB][KEEP];      // c values of selected candidates
__device__ float gSelScore[3][NB][KEEP];
__device__ float gData[2][NB][NCAND];       // tanh'd survivor-expanded values (A, B)
__device__ float gScoresL[2][NB][NCAND];    // candidate scores layer1, layer2

__device__ __forceinline__ unsigned int fkey(float f) {
    unsigned int u = __float_as_uint(f);
    return (u & 0x80000000u) ? ~u : (u | 0x80000000u);  // order-preserving map
}

// ---------------- U precompute: U[i][h] = sum_o sw1[h*fo+o] * W[o*256+i] ----------
__global__ void kU(const float* __restrict__ W, const float* __restrict__ sw1,
                   int l, int fo) {
    __shared__ float Wc[256][9];            // 8 columns of W, padded
    int tid = threadIdx.x;
    int i0 = blockIdx.x * 8;
    if (tid < fo) {
        const float* wr = W + tid * 256 + i0;
        #pragma unroll
        for (int j = 0; j < 8; j++) Wc[tid][j] = wr[j];
    }
    __syncthreads();
    int li = tid & 7, h = tid >> 3;         // 8 i's x 32 h's
    float acc = 0.f;
    for (int o = 0; o < fo; o++)
        acc = fmaf(__ldg(&sw1[h * fo + o]), Wc[o][li], acc);
    gU[l][i0 + li][h] = acc;
}

// ---------------- layer-0 scores: c = x[b,i] -------------------------------------
__global__ void kScore0(const float* __restrict__ x, const float* __restrict__ sb1,
                        const float* __restrict__ sw2, const float* __restrict__ sb2) {
    int b = blockIdx.x, i = threadIdx.x;
    float c = x[b * 256 + i];
    float acc = 0.f;
    #pragma unroll
    for (int h = 0; h < 32; h++) {
        float t = fmaf(c, gU[0][i][h], __ldg(&sb1[h]));
        acc = fmaf(__ldg(&sw2[h]), fmaxf(t, 0.f), acc);
    }
    gScore0[b][i] = acc + sb2[0];
}

// ------- fused expand: v = tanh(Wprev[i, ip_k] * c_k); score next-layer cand ------
__global__ void kExpand(const float* __restrict__ Wprev, int l, int prevStage,
                        int outSlot,
                        const float* __restrict__ sb1, const float* __restrict__ sw2,
                        const float* __restrict__ sb2) {
    __shared__ float sU[256 * 33];          // padded: sU[i*33+h], conflict-free
    __shared__ int   sIp[KEEP];
    __shared__ float sCv[KEEP];
    __shared__ float sB1[32], sW2[32];
    int b = blockIdx.y, tid = threadIdx.x;
    const float* Ul = &gU[l][0][0];
    for (int idx = tid; idx < 8192; idx += 256)
        sU[(idx >> 5) * 33 + (idx & 31)] = Ul[idx];
    if (tid < KEEP) {
        sIp[tid] = gSelIdx[prevStage][b][tid] & 255;
        sCv[tid] = gSelVal[prevStage][b][tid];
    }
    if (tid < 32) { sB1[tid] = sb1[tid]; sW2[tid] = sw2[tid]; }
    __syncthreads();
    float b2 = sb2[0];
    int base = blockIdx.x * 1024;
    float* dO = gData[outSlot][b];
    float* sO = gScoresL[outSlot][b];
    #pragma unroll
    for (int j = 0; j < 4; j++) {
        int cand = base + j * 256 + tid;    // cand = k*256 + i (matches p*Fin+i)
        int k = cand >> 8, i = cand & 255;
        float raw = __ldg(&Wprev[i * 256 + sIp[k]]) * sCv[k];
        float v = tanhf(raw);
        dO[cand] = v;                       // tanh'd value feeding next layer
        float acc = 0.f;
        const float* Ui = &sU[i * 33];
        #pragma unroll
        for (int h = 0; h < 32; h++) {
            float t = fmaf(v, Ui[h], sB1[h]);
            acc = fmaf(sW2[h], fmaxf(t, 0.f), acc);
        }
        sO[cand] = acc + b2;
    }
}

// -------- exact top-100 select (binary search on uint keys), optional finalize ----
__global__ __launch_bounds__(1024) void kSelect(int srcStage, const float* __restrict__ x,
                                                int finalize, const float* __restrict__ W2,
                                                float* __restrict__ out) {
    extern __shared__ unsigned int keys[];
    __shared__ int sCnt, sCntG, sCntE;
    __shared__ int sEq[1024];
    __shared__ int sSelI[KEEP];
    __shared__ float sSelV[KEEP], sSelS[KEEP], sWC[KEEP];
    int b = blockIdx.x, tid = threadIdx.x, nt = blockDim.x;
    int n; const float* sc; const float* vals;
    if (srcStage == 0)      { n = 256;   sc = &gScore0[b][0];      vals = x + b * 256; }
    else if (srcStage == 1) { n = NCAND; sc = &gScoresL[0][b][0];  vals = &gData[0][b][0]; }
    else                    { n = NCAND; sc = &gScoresL[1][b][0];  vals = &gData[1][b][0]; }

    for (int idx = tid; idx < n; idx += nt) keys[idx] = fkey(sc[idx]);
    __syncthreads();

    // binary search for T = KEEP-th largest key: largest v with count(key >= v) >= KEEP
    unsigned int lo = 0u, hi = 0xFFFFFFFFu;
    while (lo < hi) {
        if (tid == 0) sCnt = 0;
        __syncthreads();
        unsigned int mid = lo + ((hi - lo) >> 1) + ((hi - lo) & 1u);  // upper mid
        int c = 0;
        for (int idx = tid; idx < n; idx += nt) c += (keys[idx] >= mid) ? 1 : 0;
        c = __reduce_add_sync(0xFFFFFFFFu, c);
        if ((tid & 31) == 0 && c) atomicAdd(&sCnt, c);
        __syncthreads();
        int total = sCnt;
        __syncthreads();
        if (total >= KEEP) lo = mid; else hi = mid - 1;
    }
    unsigned int T = lo;

    if (tid == 0) { sCntG = 0; sCntE = 0; }
    __syncthreads();
    for (int idx = tid; idx < n; idx += nt) {
        unsigned int kk = keys[idx];
        if (kk > T)       { int p = atomicAdd(&sCntG, 1); sSelI[p] = idx; }
        else if (kk == T) { int p = atomicAdd(&sCntE, 1); if (p < 1024) sEq[p] = idx; }
    }
    __syncthreads();
    if (tid == 0) {
        int G = sCntG;
        int E = KEEP - G;
        int ne = sCntE < 1024 ? sCntE : 1024;
        for (int e = 0; e < E && e < ne; e++) {      // take equals by smallest index
            int bmin = 0x7FFFFFFF, bp = 0;
            for (int q = 0; q < ne; q++) if (sEq[q] < bmin) { bmin = sEq[q]; bp = q; }
            sSelI[G + e] = bmin; sEq[bp] = 0x7FFFFFFF;
        }
    }
    __syncthreads();
    if (tid < KEEP) {
        int idx = sSelI[tid];
        float v = vals[idx];
        float s = sc[idx];
        sSelV[tid] = v; sSelS[tid] = s;
        gSelIdx[srcStage][b][tid]   = idx;
        gSelVal[srcStage][b][tid]   = v;
        gSelScore[srcStage][b][tid] = s;
    }
    __syncthreads();

    if (finalize) {
        if (tid == 0) {
            float mx = -INFINITY;
            for (int q = 0; q < KEEP; q++) mx = fmaxf(mx, sSelS[q]);
            float Z = 0.f;
            for (int q = 0; q < KEEP; q++) { float e = expf(sSelS[q] - mx); sWC[q] = e; Z += e; }
            float iz = 1.f / Z;
            for (int q = 0; q < KEEP; q++) sWC[q] = sWC[q] * iz * sSelV[q];
        }
        __syncthreads();
        if (tid < 128) {
            float acc = 0.f;
            for (int q = 0; q < KEEP; q++)
                acc = fmaf(sWC[q], __ldg(&W2[tid * 256 + (sSelI[q] & 255)]), acc);
            out[b * 128 + tid] = acc;
        }
    }
}

// ---------------------------------------------------------------------------------
extern "C" void kernel_launch(void* const* d_in, const int* in_sizes, int n_in,
                              void* d_out, int out_size) {
    const float *x, *W[3], *sw1[3], *sb1[3], *sw2[3], *sb2[3];
    x = (const float*)d_in[0];
    if (n_in >= 16 && in_sizes[2] == 65536) {
        // signature order: x, W0, W1, W2, then scorer quads
        for (int l = 0; l < 3; l++) W[l] = (const float*)d_in[1 + l];
        for (int l = 0; l < 3; l++) {
            int base = 4 + l * 4;
            sw1[l] = (const float*)d_in[base];     sb1[l] = (const float*)d_in[base + 1];
            sw2[l] = (const float*)d_in[base + 2]; sb2[l] = (const float*)d_in[base + 3];
        }
    } else {
        // setup_inputs dict order: x, then per layer: W, sw1, sb1, sw2, sb2
        for (int l = 0; l < 3; l++) {
            int base = 1 + l * 5;
            W[l]   = (const float*)d_in[base];
            sw1[l] = (const float*)d_in[base + 1]; sb1[l] = (const float*)d_in[base + 2];
            sw2[l] = (const float*)d_in[base + 3]; sb2[l] = (const float*)d_in[base + 4];
        }
    }
    float* out = (float*)d_out;

    cudaFuncSetAttribute(kSelect, cudaFuncAttributeMaxDynamicSharedMemorySize, NCAND * 4);

    kU<<<32, 256>>>(W[0], sw1[0], 0, 256);
    kU<<<32, 256>>>(W[1], sw1[1], 1, 256);
    kU<<<32, 256>>>(W[2], sw1[2], 2, 128);
    kScore0<<<16, 256>>>(x, sb1[0], sw2[0], sb2[0]);
    kSelect<<<16, 1024, 256 * 4>>>(0, x, 0, (const float*)0, (float*)0);
    kExpand<<<dim3(25, 16), 256>>>(W[0], 1, 0, 0, sb1[1], sw2[1], sb2[1]);
    kSelect<<<16, 1024, NCAND * 4>>>(1, x, 0, (const float*)0, (float*)0);
    kExpand<<<dim3(25, 16), 256>>>(W[1], 2, 1, 1, sb1[2], sw2[2], sb2[2]);
    kSelect<<<16, 1024, NCAND * 4>>>(2, x, 1, W[2], out);
}

// round 2
// speedup vs baseline: 1.4672x; 1.4672x over previous
#include <cuda_runtime.h>
#include <math.h>

#define KEEP 100
#define NCAND 25600
#define NBLK 96
#define NT 1024

struct Params {
    const float* x;
    const float* W[3];
    const float* sw1[3]; const float* sb1[3];
    const float* sw2[3]; const float* sb2[3];
    float* out;
};

// ---------------- device scratch (no allocations) ----------------
__device__ float    gU[3][256][32];          // U_l[i][h] = sum_o sw1[h,o]*W[o,i]
__device__ int      gSelIdx[2][16][KEEP];    // selected feature index i (0..255)
__device__ float    gSelVal[2][16][KEEP];    // scalar value of selected path
__device__ unsigned gKeysA[16][NCAND];       // stage-1 score keys
__device__ unsigned gKeysB[16][NCAND];       // stage-2 score keys
__device__ unsigned gBarCt[8];               // grid barrier counters (self-reset)
__device__ unsigned gBarGen[8];              // grid barrier generations (monotonic)

struct SM {
    float    sU[256 * 33];                   // padded U tile / phase-A partials
    unsigned hist[256];
    unsigned cum[256];
    int      selI[KEEP];
    float    selS[KEEP];
    int      eq[512];
    int      ip[KEEP];
    float    cv[KEEP];
    float    b1c[32], w2c[32];
    float    wc[KEEP];
    int      cnt[4];                         // 0:G 1:E 2:byte 3:rank
};

__device__ __forceinline__ unsigned fkey(float f) {
    unsigned u = __float_as_uint(f);
    return (u & 0x80000000u) ? ~u : (u | 0x80000000u);
}
__device__ __forceinline__ float ikey(unsigned k) {
    return __uint_as_float((k & 0x80000000u) ? (k & 0x7FFFFFFFu) : ~k);
}

// ---- software grid barrier: each index used exactly once per launch ----
__device__ __forceinline__ void gridbar(int k) {
    __threadfence();
    __syncthreads();
    if (threadIdx.x == 0) {
        unsigned g = *(volatile unsigned*)&gBarGen[k];
        unsigned old = atomicAdd(&gBarCt[k], 1u);
        if (old == NBLK - 1u) {
            atomicExch(&gBarCt[k], 0u);      // reset for next graph replay
            __threadfence();
            atomicAdd(&gBarGen[k], 1u);
        } else {
            while (*(volatile unsigned*)&gBarGen[k] == g) { __nanosleep(64); }
        }
    }
    __syncthreads();
    __threadfence();
}

// ---- exact top-KEEP: 4-pass radix threshold + collect, deterministic order ----
__device__ void topk_select(unsigned* keys, int n, SM* sm, int tid) {
    unsigned prefix = 0u;
    int r = KEEP;
    #pragma unroll
    for (int shift = 24; shift >= 0; shift -= 8) {
        if (tid < 256) sm->hist[tid] = 0u;
        __syncthreads();
        unsigned pm = (shift == 24) ? 0u : (0xFFFFFFFFu << (shift + 8));
        for (int idx = tid; idx < n; idx += NT) {
            unsigned k = keys[idx];
            if ((k & pm) == prefix) atomicAdd(&sm->hist[(k >> shift) & 255], 1u);
        }
        __syncthreads();
        if (tid < 32) {                      // warp-0 suffix scan over 256 bins
            int base = tid * 8;
            unsigned s[8]; unsigned run = 0u;
            #pragma unroll
            for (int j = 7; j >= 0; j--) { run += sm->hist[base + j]; s[j] = run; }
            unsigned t = run;
            #pragma unroll
            for (int off = 1; off < 32; off <<= 1) {
                unsigned u = __shfl_down_sync(0xFFFFFFFFu, t, off);
                if (tid + off < 32) t += u;
            }
            unsigned above = t - run;        // totals of lanes > tid
            #pragma unroll
            for (int j = 0; j < 8; j++) sm->cum[base + j] = s[j] + above;
        }
        __syncthreads();
        if (tid < 256) {
            unsigned c  = sm->cum[tid];
            unsigned cn = (tid < 255) ? sm->cum[tid + 1] : 0u;
            if (c >= (unsigned)r && cn < (unsigned)r) {
                sm->cnt[2] = tid;
                sm->cnt[3] = r - (int)cn;
            }
        }
        __syncthreads();
        prefix |= ((unsigned)sm->cnt[2]) << shift;
        r = sm->cnt[3];
        __syncthreads();
    }
    unsigned T = prefix;                     // exact KEEP-th largest key
    if (tid == 0) { sm->cnt[0] = 0; sm->cnt[1] = 0; }
    __syncthreads();
    for (int idx = tid; idx < n; idx += NT) {
        unsigned k = keys[idx];
        if (k > T)       { int pp = atomicAdd(&sm->cnt[0], 1); sm->selI[pp] = idx; }
        else if (k == T) { int pp = atomicAdd(&sm->cnt[1], 1); if (pp < 512) sm->eq[pp] = idx; }
    }
    __syncthreads();
    if (tid == 0) {                          // ties: take smallest indices
        int G = sm->cnt[0], E = KEEP - G;
        int ne = sm->cnt[1] < 512 ? sm->cnt[1] : 512;
        for (int e = 0; e < E; e++) {
            int bmin = 0x7FFFFFFF, bp = 0;
            for (int q = 0; q < ne; q++) if (sm->eq[q] < bmin) { bmin = sm->eq[q]; bp = q; }
            sm->selI[G + e] = bmin; sm->eq[bp] = 0x7FFFFFFF;
        }
    }
    __syncthreads();
    int myIdx = 0, rank = 0;                 // deterministic order: sort by index
    if (tid < KEEP) {
        myIdx = sm->selI[tid];
        for (int q = 0; q < KEEP; q++) rank += (sm->selI[q] < myIdx) ? 1 : 0;
    }
    __syncthreads();
    if (tid < KEEP) sm->selI[rank] = myIdx;
    __syncthreads();
}

// ---- fused scoring of one stage's 25600 candidates (chunked over 96 blocks) ----
__device__ void score_stage(const Params& p, SM* sm, unsigned* dstKeys,
                            int l, int prevStage, const float* Wprev,
                            int b, int c0, int c1, int tid) {
    const float* Ug = &gU[l][0][0];
    for (int idx = tid; idx < 8192; idx += NT)
        sm->sU[(idx >> 5) * 33 + (idx & 31)] = Ug[idx];
    if (tid < KEEP) {
        sm->ip[tid] = gSelIdx[prevStage][b][tid];
        sm->cv[tid] = gSelVal[prevStage][b][tid];
    }
    if (tid < 32) { sm->b1c[tid] = p.sb1[l][tid]; sm->w2c[tid] = p.sw2[l][tid]; }
    __syncthreads();
    float b2 = p.sb2[l][0];
    for (int cand = c0 + tid; cand < c1; cand += NT) {
        int k = cand >> 8, i = cand & 255;
        float v = tanhf(Wprev[i * 256 + sm->ip[k]] * sm->cv[k]);
        float acc = 0.f;
        const float* Ui = &sm->sU[i * 33];
        #pragma unroll
        for (int h = 0; h < 32; h++) {
            float t = fmaf(v, Ui[h], sm->b1c[h]);
            acc = fmaf(sm->w2c[h], fmaxf(t, 0.f), acc);
        }
        dstKeys[cand] = fkey(acc + b2);
    }
}

__global__ void __launch_bounds__(NT, 1) kAll(Params p) {
    extern __shared__ unsigned keys[];
    __shared__ SM sm;
    const int tid = threadIdx.x;
    const int g = blockIdx.x;

    // ---------- Phase A: U_l = sw1_l @ W_l  (96 blocks, 256 outputs each) ----------
    {
        int l = g >> 5;
        int i0 = (g & 31) << 3;
        const float* W; const float* s1; int fo;
        if (l == 0)      { W = p.W[0]; s1 = p.sw1[0]; fo = 256; }
        else if (l == 1) { W = p.W[1]; s1 = p.sw1[1]; fo = 256; }
        else             { W = p.W[2]; s1 = p.sw1[2]; fo = 128; }
        int oi = tid & 255, q = tid >> 8;
        int di = oi >> 5, h = oi & 31;
        int seg = fo >> 2;
        const float* wcol = W + i0 + di;
        const float* srow = s1 + h * fo;
        float acc = 0.f;
        for (int o = q * seg; o < (q + 1) * seg; o++)
            acc = fmaf(srow[o], wcol[o * 256], acc);
        sm.sU[oi * 4 + q] = acc;
        __syncthreads();
        if (q == 0)
            gU[l][i0 + di][h] = sm.sU[oi * 4] + sm.sU[oi * 4 + 1]
                              + sm.sU[oi * 4 + 2] + sm.sU[oi * 4 + 3];
    }
    gridbar(0);

    // ---------- Phase B: score0 + select0 (16 blocks) ----------
    if (g < 16) {
        int b = g;
        if (tid < 256) {
            float c = p.x[b * 256 + tid];
            const float4* Ur = (const float4*)&gU[0][tid][0];
            float acc = 0.f;
            #pragma unroll
            for (int j = 0; j < 8; j++) {
                float4 u4 = Ur[j];
                float t0 = fmaf(c, u4.x, p.sb1[0][j * 4 + 0]);
                float t1 = fmaf(c, u4.y, p.sb1[0][j * 4 + 1]);
                float t2 = fmaf(c, u4.z, p.sb1[0][j * 4 + 2]);
                float t3 = fmaf(c, u4.w, p.sb1[0][j * 4 + 3]);
                acc = fmaf(p.sw2[0][j * 4 + 0], fmaxf(t0, 0.f), acc);
                acc = fmaf(p.sw2[0][j * 4 + 1], fmaxf(t1, 0.f), acc);
                acc = fmaf(p.sw2[0][j * 4 + 2], fmaxf(t2, 0.f), acc);
                acc = fmaf(p.sw2[0][j * 4 + 3], fmaxf(t3, 0.f), acc);
            }
            keys[tid] = fkey(acc + p.sb2[0][0]);
        }
        __syncthreads();
        topk_select(keys, 256, &sm, tid);
        if (tid < KEEP) {
            int idx = sm.selI[tid];
            gSelIdx[0][b][tid] = idx;
            gSelVal[0][b][tid] = p.x[b * 256 + idx];
        }
    }
    gridbar(1);

    // ---------- Phase C: stage-1 candidate scoring (96 blocks, 6 chunks/batch) ----------
    {
        int b = g & 15, chunk = g >> 4;
        int c0 = chunk * 4267;
        int c1 = c0 + 4267; if (c1 > NCAND) c1 = NCAND;
        score_stage(p, &sm, &gKeysA[b][0], 1, 0, p.W[0], b, c0, c1, tid);
    }
    gridbar(2);

    // ---------- Phase D: select1 (16 blocks) ----------
    if (g < 16) {
        int b = g;
        for (int idx = tid; idx < NCAND; idx += NT) keys[idx] = gKeysA[b][idx];
        __syncthreads();
        topk_select(keys, NCAND, &sm, tid);
        if (tid < KEEP) {
            int cand = sm.selI[tid];
            int k = cand >> 8, i = cand & 255;
            int ip = gSelIdx[0][b][k];
            float cv = gSelVal[0][b][k];
            gSelIdx[1][b][tid] = i;
            gSelVal[1][b][tid] = tanhf(p.W[0][i * 256 + ip] * cv);
        }
    }
    gridbar(3);

    // ---------- Phase E: stage-2 candidate scoring ----------
    {
        int b = g & 15, chunk = g >> 4;
        int c0 = chunk * 4267;
        int c1 = c0 + 4267; if (c1 > NCAND) c1 = NCAND;
        score_stage(p, &sm, &gKeysB[b][0], 2, 1, p.W[1], b, c0, c1, tid);
    }
    gridbar(4);

    // ---------- Phase F: select2 + softmax + output (16 blocks) ----------
    if (g < 16) {
        int b = g;
        for (int idx = tid; idx < NCAND; idx += NT) keys[idx] = gKeysB[b][idx];
        __syncthreads();
        topk_select(keys, NCAND, &sm, tid);
        if (tid < KEEP) {
            int cand = sm.selI[tid];
            int k = cand >> 8, i = cand & 255;
            int ip = gSelIdx[1][b][k];
            float cv = gSelVal[1][b][k];
            sm.wc[tid]   = tanhf(p.W[1][i * 256 + ip] * cv);   // data value (layer2->no tanh after)
            sm.selS[tid] = ikey(keys[cand]);                   // exact score
        }
        __syncthreads();
        if (tid == 0) {
            float mx = -INFINITY;
            for (int q = 0; q < KEEP; q++) mx = fmaxf(mx, sm.selS[q]);
            float Z = 0.f;
            for (int q = 0; q < KEEP; q++) { float e = expf(sm.selS[q] - mx); sm.cv[q] = e; Z += e; }
            float iz = 1.f / Z;
            for (int q = 0; q < KEEP; q++) sm.cv[q] = sm.cv[q] * iz * sm.wc[q];
        }
        __syncthreads();
        if (tid < 128) {
            float acc = 0.f;
            #pragma unroll 4
            for (int q = 0; q < KEEP; q++)
                acc = fmaf(sm.cv[q], p.W[2][tid * 256 + (sm.selI[q] & 255)], acc);
            p.out[b * 128 + tid] = acc;
        }
    }
}

// ---------------------------------------------------------------------------------
extern "C" void kernel_launch(void* const* d_in, const int* in_sizes, int n_in,
                              void* d_out, int out_size) {
    Params p;
    p.x = (const float*)d_in[0];
    if (n_in >= 16 && in_sizes[2] == 65536) {
        for (int l = 0; l < 3; l++) p.W[l] = (const float*)d_in[1 + l];
        for (int l = 0; l < 3; l++) {
            int base = 4 + l * 4;
            p.sw1[l] = (const float*)d_in[base];     p.sb1[l] = (const float*)d_in[base + 1];
            p.sw2[l] = (const float*)d_in[base + 2]; p.sb2[l] = (const float*)d_in[base + 3];
        }
    } else {
        for (int l = 0; l < 3; l++) {
            int base = 1 + l * 5;
            p.W[l]   = (const float*)d_in[base];
            p.sw1[l] = (const float*)d_in[base + 1]; p.sb1[l] = (const float*)d_in[base + 2];
            p.sw2[l] = (const float*)d_in[base + 3]; p.sb2[l] = (const float*)d_in[base + 4];
        }
    }
    p.out = (float*)d_out;

    static int attr_set = 0;
    if (!attr_set) {
        cudaFuncSetAttribute(kAll, cudaFuncAttributeMaxDynamicSharedMemorySize, NCAND * 4);
        attr_set = 1;
    }
    kAll<<<NBLK, NT, NCAND * 4>>>(p);
}